// round 13
// baseline (speedup 1.0000x reference)
#include <cuda_runtime.h>
#include <cuda_fp16.h>
#include <cstdint>

#define NN   8192
#define FIN  256
#define FOUT 128
#define NC   128        // j-chunks of 64
#define BM   32         // rows per CTA in main kernel
#define GRID_MAIN (NN / BM)   // 256

// ---------------- scratch (static device globals; no allocation) ----------------
__device__ __align__(16) __half g_Wh16[(size_t)NN * FOUT];  // [row j][col c] fp16
__device__ __align__(16) uint2    g_A1[NN / 2];   // per j-pair {f2h2, E2h2}
__device__ __align__(16) unsigned g_A2[NN / 2];   // per j-pair G2h2
__device__ __half g_nf1h[NN];   // (half)(-f1)
__device__ __half g_H1h [NN];   // (half)exp(-0.8 f1)

__device__ __forceinline__ uint32_t sptr(const void* p) {
    return (uint32_t)__cvta_generic_to_shared(p);
}
__device__ __forceinline__ __half2 u2h(uint32_t u) { return *(__half2*)&u; }
__device__ __forceinline__ uint32_t h2u(__half2 h) { return *(uint32_t*)&h; }

// =====================================================================
// Kernel 1: Wh = h @ W (fp32 SIMT GEMM), cp.async double-buffered.
// BM=16, grid 512 (R8 lesson: grid-limited occupancy; 512 CTAs -> 3.5/SM).
// Fused fp16 Wh output + f1/f2 reductions + packed fp16 j-tables.
// =====================================================================
__global__ __launch_bounds__(256, 4) void wh_gemm_kernel(
    const float* __restrict__ h, const float* __restrict__ Wm,
    const float* __restrict__ a)
{
    __shared__ float hs[2][16][36];
    __shared__ float Ws[2][32][132];
    const int tid = threadIdx.x;
    const int i0  = blockIdx.x * 16;
    const int ty  = tid >> 4, tx = tid & 15;   // ty = row 0..15, tx = col group

    auto stage = [&](int kt) {
        int k0 = kt * 32, buf = kt & 1;
        if (tid < 128) {   // h tile 16x32
            int r = tid >> 3, c = (tid & 7) * 4;
            asm volatile("cp.async.cg.shared.global [%0],[%1],16;\n"
                :: "r"(sptr(&hs[buf][r][c])),
                   "l"(&h[(size_t)(i0 + r) * FIN + k0 + c]));
        }
        {   // W tile 32x128
            int r = tid >> 3, c = (tid & 7) * 16;
#pragma unroll
            for (int q = 0; q < 4; q++)
                asm volatile("cp.async.cg.shared.global [%0],[%1],16;\n"
                    :: "r"(sptr(&Ws[buf][r][c + 4*q])),
                       "l"(&Wm[(size_t)(k0 + r) * FOUT + c + 4*q]));
        }
        asm volatile("cp.async.commit_group;\n");
    };

    float acc[8];
#pragma unroll
    for (int v = 0; v < 8; v++) acc[v] = 0.0f;

    stage(0);
    for (int kt = 0; kt < 8; kt++) {
        asm volatile("cp.async.wait_group 0;\n");
        __syncthreads();
        if (kt < 7) stage(kt + 1);
        const int buf = kt & 1;
#pragma unroll 8
        for (int k = 0; k < 32; k++) {
            float a0 = hs[buf][ty][k];
            float4 b0 = *(const float4*)&Ws[buf][k][8*tx];
            float4 b1 = *(const float4*)&Ws[buf][k][8*tx + 4];
            acc[0] = fmaf(a0, b0.x, acc[0]);
            acc[1] = fmaf(a0, b0.y, acc[1]);
            acc[2] = fmaf(a0, b0.z, acc[2]);
            acc[3] = fmaf(a0, b0.w, acc[3]);
            acc[4] = fmaf(a0, b1.x, acc[4]);
            acc[5] = fmaf(a0, b1.y, acc[5]);
            acc[6] = fmaf(a0, b1.z, acc[6]);
            acc[7] = fmaf(a0, b1.w, acc[7]);
        }
    }

    // ---- epilogue: fp16 Wh + f1/f2 + packed tables ----
    float f1a = 0.f, f2a = 0.f;
    {
        int row = i0 + ty;
#pragma unroll
        for (int q = 0; q < 4; q++) {
            *(__half2*)&g_Wh16[(size_t)row * FOUT + 8*tx + 2*q] =
                __floats2half2_rn(acc[2*q], acc[2*q+1]);
        }
#pragma unroll
        for (int v = 0; v < 8; v++) {
            int col = 8*tx + v;
            f1a = fmaf(acc[v], a[col],        f1a);
            f2a = fmaf(acc[v], a[FOUT + col], f2a);
        }
    }
    // reduce over tx within each half-warp (lanes 0-15 / 16-31 independent)
#pragma unroll
    for (int o = 8; o > 0; o >>= 1) {
        f1a += __shfl_xor_sync(0xffffffffu, f1a, o);
        f2a += __shfl_xor_sync(0xffffffffu, f2a, o);
    }
    // lane 0 holds row 2w, lane 16 holds row 2w+1 (w = warp in block)
    float f1b = __shfl_xor_sync(0xffffffffu, f1a, 16);
    float f2b = __shfl_xor_sync(0xffffffffu, f2a, 16);
    if ((tid & 31) == 0) {
        int w = tid >> 5;
        int row0 = i0 + 2*w;
        int k = row0 >> 1;          // j-pair index
        uint2 a1v;
        a1v.x = h2u(__floats2half2_rn(f2a, f2b));
        a1v.y = h2u(__floats2half2_rn(expf(f2a), expf(f2b)));
        g_A1[k] = a1v;
        g_A2[k] = h2u(__floats2half2_rn(expf(0.2f*f2a), expf(0.2f*f2b)));
        g_nf1h[row0]     = __float2half(-f1a);
        g_nf1h[row0 + 1] = __float2half(-f1b);
        g_H1h[row0]      = __float2half(expf(-0.8f * f1a));
        g_H1h[row0 + 1]  = __float2half(expf(-0.8f * f1b));
    }
}

// =====================================================================
// Kernel 2: fused masked-softmax-attention, fp16 mma.sync (R10 skeleton,
// unchanged ring/commit/barrier structure) + R12's packed-half2 pgen.
// Denominator: fp32 per-thread + shfl tree (R10 style — the R12 den-MMA
// unbalanced warps and regressed). 512 threads, 2m x 8n, m16n16 tiles.
// adj ring x3, sP x3, sB x4; commit [B(ch+2)][A(ch+3)] + wait_group 4;
// ONE __syncthreads per chunk.
// =====================================================================
__device__ __forceinline__ void mma_fp16(float* c, const uint32_t* a,
                                         uint32_t b0, uint32_t b1)
{
    asm volatile(
        "mma.sync.aligned.m16n8k16.row.col.f32.f16.f16.f32 "
        "{%0,%1,%2,%3},{%4,%5,%6,%7},{%8,%9},{%0,%1,%2,%3};\n"
        : "+f"(c[0]), "+f"(c[1]), "+f"(c[2]), "+f"(c[3])
        : "r"(a[0]), "r"(a[1]), "r"(a[2]), "r"(a[3]), "r"(b0), "r"(b1));
}

#define ADJ_SLOT 8192u       // 32 x 64 ints
#define SP_SLOT  4608u       // 32 x 72 halfs (144B rows)
#define SB_SLOT  17408u      // 64 x 136 halfs (272B rows)
#define DYN_SMEM (3*ADJ_SLOT + 3*SP_SLOT + 4*SB_SLOT)   // 108032

__global__ __launch_bounds__(512, 2) void gat_main_kernel(
    const int* __restrict__ adj, float* __restrict__ out)
{
    extern __shared__ char dynsm[];
    __shared__ float sden[BM];

    const int tid  = threadIdx.x;
    const int lane = tid & 31;
    const int warp = tid >> 5;     // 0..15
    const int r    = tid >> 4;     // 0..31  (pgen/adj row)
    const int cq   = tid & 15;     // col group of 4
    const int i0   = blockIdx.x * BM;
    const int wm   = warp & 1;     // m16 position (2)
    const int wn   = warp >> 1;    // n16 position (8)

    const uint32_t adjS = sptr(dynsm);
    const uint32_t spS  = adjS + 3 * ADJ_SLOT;
    const uint32_t sbS  = spS  + 3 * SP_SLOT;

    const __half2 nf1r2 = __half2half2(g_nf1h[i0 + r]);
    const __half2 H1r2  = __half2half2(g_H1h [i0 + r]);
    float den = 0.0f;

    float acc[2][4];
#pragma unroll
    for (int nf = 0; nf < 2; nf++)
#pragma unroll
        for (int q = 0; q < 4; q++) acc[nf][q] = 0.0f;

    // ---- stage helpers (each always commits exactly one group) ----
    auto stage_adj = [&](int ch) {
        if (ch < NC) {
            const int* src = &adj[(size_t)(i0 + r) * NN + ch * 64 + 4 * cq];
            uint32_t dst = adjS + (uint32_t)(ch % 3) * ADJ_SLOT
                         + (uint32_t)(r * 256 + 16 * cq);
            asm volatile("cp.async.cg.shared.global [%0],[%1],16;\n" :: "r"(dst), "l"(src));
        }
        asm volatile("cp.async.commit_group;\n");
    };
    auto stage_B = [&](int ch) {
        if (ch < NC) {
            const int j0 = ch * 64;
            uint32_t base = sbS + (uint32_t)(ch & 3) * SB_SLOT;
#pragma unroll
            for (int i = 0; i < 2; i++) {
                int seg = tid + 512 * i;          // 0..1023
                int rr = seg >> 4, ss = seg & 15;
                const __half* src = &g_Wh16[(size_t)(j0 + rr) * FOUT + 8 * ss];
                uint32_t dst = base + (uint32_t)(rr * 272 + 16 * ss);
                asm volatile("cp.async.cg.shared.global [%0],[%1],16;\n" :: "r"(dst), "l"(src));
            }
        }
        asm volatile("cp.async.commit_group;\n");
    };

    // pgen: packed half2 tables, mask-select; fp32 den from the SAME
    // fp16 weights the MMA consumes.
    auto pgen_rest = [&](int ch, uint4 t1, uint2 t2) {
        uint32_t aoff = adjS + (uint32_t)(ch % 3) * ADJ_SLOT
                      + (uint32_t)(r * 256 + 16 * cq);
        int4 a0;
        asm volatile("ld.shared.v4.b32 {%0,%1,%2,%3},[%4];"
                     : "=r"(a0.x), "=r"(a0.y), "=r"(a0.z), "=r"(a0.w) : "r"(aoff));
        uint32_t gA = __hgt2_mask(u2h(t1.x), nf1r2);
        uint32_t gB = __hgt2_mask(u2h(t1.z), nf1r2);
        uint32_t tA = h2u(__hmul2(H1r2, u2h(t2.x)));
        uint32_t tB = h2u(__hmul2(H1r2, u2h(t2.y)));
        uint32_t selA = (t1.y & gA) | (tA & ~gA);
        uint32_t selB = (t1.w & gB) | (tB & ~gB);
        uint32_t mA = (a0.x > 0 ? 0xFFFFu : 0u) | (a0.y > 0 ? 0xFFFF0000u : 0u);
        uint32_t mB = (a0.z > 0 ? 0xFFFFu : 0u) | (a0.w > 0 ? 0xFFFF0000u : 0u);
        uint32_t wA = selA & mA, wB = selB & mB;
        float2 fa = __half22float2(u2h(wA));
        float2 fb = __half22float2(u2h(wB));
        den += fa.x + fa.y + fb.x + fb.y;
        uint32_t dst = spS + (uint32_t)(ch % 3) * SP_SLOT
                     + (uint32_t)(r * 144 + 8 * cq);
        asm volatile("st.shared.v2.b32 [%0],{%1,%2};"
                     :: "r"(dst), "r"(wA), "r"(wB) : "memory");
    };

    auto mma_phase = [&](int ch) {
        uint32_t sp = spS + (uint32_t)(ch % 3) * SP_SLOT;
        uint32_t sb = sbS + (uint32_t)(ch & 3) * SB_SLOT;
        const int mi = lane >> 3, l7 = lane & 7;
        uint32_t spA = sp + (uint32_t)((16*wm + ((mi & 1) << 3) + l7) * 144
                                       + (((mi >> 1) << 3)) * 2);
        uint32_t sbB = sb + (uint32_t)((((mi & 1) << 3) + l7) * 272
                                       + (16*wn + ((mi >> 1) << 3)) * 2);
#pragma unroll
        for (int kk = 0; kk < 4; kk++) {
            uint32_t afr[4];
            asm volatile(
                "ldmatrix.sync.aligned.m8n8.x4.shared.b16 {%0,%1,%2,%3},[%4];\n"
                : "=r"(afr[0]), "=r"(afr[1]), "=r"(afr[2]), "=r"(afr[3])
                : "r"(spA + (uint32_t)(32 * kk)));
            uint32_t b[4];
            asm volatile(
                "ldmatrix.sync.aligned.m8n8.x4.trans.shared.b16 {%0,%1,%2,%3},[%4];\n"
                : "=r"(b[0]), "=r"(b[1]), "=r"(b[2]), "=r"(b[3])
                : "r"(sbB + (uint32_t)(16 * kk * 272)));
            mma_fp16(acc[0], afr, b[0], b[1]);
            mma_fp16(acc[1], afr, b[2], b[3]);
        }
    };

    // ---- prologue: commits [A0][B0][A1][B1][A2] ----
    stage_adj(0);
    stage_B(0);
    stage_adj(1);
    stage_B(1);
    stage_adj(2);
    {
        uint4 t1 = __ldg((const uint4*)&g_A1[2 * cq]);
        uint2 t2 = __ldg((const uint2*)&g_A2[2 * cq]);
        asm volatile("cp.async.wait_group 4;\n");   // forces A0
        pgen_rest(0, t1, t2);
    }

    // ---- main loop: commits per iter [B(ch+2)][A(ch+3)], 1 barrier ----
    for (int ch = 0; ch < NC; ch++) {
        stage_B(ch + 2);
        stage_adj(ch + 3);
        const int chn = ch + 1;
        uint4 t1; uint2 t2;
        if (chn < NC) {                 // hoisted: no cp.async dependency
            t1 = __ldg((const uint4*)&g_A1[chn * 32 + 2 * cq]);
            t2 = __ldg((const uint2*)&g_A2[chn * 32 + 2 * cq]);
        }
        asm volatile("cp.async.wait_group 4;\n");   // forces B(ch), A(ch+1)
        if (chn < NC) pgen_rest(chn, t1, t2);
        __syncthreads();                // publishes P(ch)/B(ch); guards reuse
        mma_phase(ch);
    }

    // ---- denominator reduction (16 threads per row) ----
    den += __shfl_xor_sync(0xffffffffu, den, 1);
    den += __shfl_xor_sync(0xffffffffu, den, 2);
    den += __shfl_xor_sync(0xffffffffu, den, 4);
    den += __shfl_xor_sync(0xffffffffu, den, 8);
    if (cq == 0) sden[r] = den;
    __syncthreads();

    // ---- epilogue: normalize, write fp32 output ----
    const int g = lane >> 2, t = lane & 3;
    {
        int row0 = 16*wm + g;
        float inv0 = 1.0f / sden[row0];
        float inv1 = 1.0f / sden[row0 + 8];
#pragma unroll
        for (int nf = 0; nf < 2; nf++) {
            int col = 16*wn + 8*nf + 2*t;
            out[(size_t)(i0 + row0)     * FOUT + col    ] = acc[nf][0] * inv0;
            out[(size_t)(i0 + row0)     * FOUT + col + 1] = acc[nf][1] * inv0;
            out[(size_t)(i0 + row0 + 8) * FOUT + col    ] = acc[nf][2] * inv1;
            out[(size_t)(i0 + row0 + 8) * FOUT + col + 1] = acc[nf][3] * inv1;
        }
    }
}

// =====================================================================
extern "C" void kernel_launch(void* const* d_in, const int* in_sizes, int n_in,
                              void* d_out, int out_size)
{
    const float* h   = (const float*)d_in[0];   // [8192,256] f32
    const int*   adj = (const int*)  d_in[1];   // [8192,8192] i32
    const float* Wm  = (const float*)d_in[2];   // [256,128] f32
    const float* a   = (const float*)d_in[3];   // [256,1] f32
    float* out = (float*)d_out;                 // [8192,128] f32

    cudaFuncSetAttribute(gat_main_kernel,
                         cudaFuncAttributeMaxDynamicSharedMemorySize, DYN_SMEM);

    wh_gemm_kernel <<<NN / 16, 256>>>(h, Wm, a);
    gat_main_kernel<<<GRID_MAIN, 512, DYN_SMEM>>>(adj, out);
}

// round 14
// speedup vs baseline: 1.1988x; 1.1988x over previous
#include <cuda_runtime.h>
#include <cuda_fp16.h>
#include <cstdint>

#define NN   8192
#define FIN  256
#define FOUT 128
#define NC   128        // j-chunks of 64
#define BM   32         // rows per CTA in main kernel
#define GRID_MAIN (NN / BM)   // 256

// ---------------- scratch (static device globals; no allocation) ----------------
__device__ __align__(16) __half g_Wh16[(size_t)NN * FOUT];  // [row j][col c] fp16
__device__ __align__(16) uint2    g_A1[NN / 2];   // per j-pair {f2h2, E2h2}
__device__ __align__(16) unsigned g_A2[NN / 2];   // per j-pair G2h2
__device__ __half g_nf1h[NN];   // (half)(-f1)
__device__ __half g_H1h [NN];   // (half)exp(-0.8 f1)

__device__ __forceinline__ uint32_t sptr(const void* p) {
    return (uint32_t)__cvta_generic_to_shared(p);
}
__device__ __forceinline__ __half2 u2h(uint32_t u) { return *(__half2*)&u; }
__device__ __forceinline__ uint32_t h2u(__half2 h) { return *(uint32_t*)&h; }

// =====================================================================
// Kernel 1: Wh = h @ W (fp32 SIMT GEMM), cp.async double-buffered.
// R10 configuration restored (BM=32, 2x8 thread tile — the R13 BM16
// variant halved per-thread ILP and regressed ~2x). Fused fp16 Wh
// output + f1/f2 reductions + packed fp16 j-tables.
// =====================================================================
__global__ __launch_bounds__(256, 2) void wh_gemm_kernel(
    const float* __restrict__ h, const float* __restrict__ Wm,
    const float* __restrict__ a)
{
    __shared__ float hs[2][32][36];
    __shared__ float Ws[2][32][132];
    const int tid = threadIdx.x;
    const int i0  = blockIdx.x * 32;
    const int ty  = tid >> 4, tx = tid & 15;

    auto stage = [&](int kt) {
        int k0 = kt * 32, buf = kt & 1;
        {   int r = tid >> 3, c = (tid & 7) * 4;
            asm volatile("cp.async.cg.shared.global [%0],[%1],16;\n"
                :: "r"(sptr(&hs[buf][r][c])),
                   "l"(&h[(size_t)(i0 + r) * FIN + k0 + c]));
        }
        {   int r = tid >> 3, c = (tid & 7) * 16;
#pragma unroll
            for (int q = 0; q < 4; q++)
                asm volatile("cp.async.cg.shared.global [%0],[%1],16;\n"
                    :: "r"(sptr(&Ws[buf][r][c + 4*q])),
                       "l"(&Wm[(size_t)(k0 + r) * FOUT + c + 4*q]));
        }
        asm volatile("cp.async.commit_group;\n");
    };

    float acc[2][8];
#pragma unroll
    for (int u = 0; u < 2; u++)
#pragma unroll
        for (int v = 0; v < 8; v++) acc[u][v] = 0.0f;

    stage(0);
    for (int kt = 0; kt < 8; kt++) {
        asm volatile("cp.async.wait_group 0;\n");
        __syncthreads();
        if (kt < 7) stage(kt + 1);
        const int buf = kt & 1;
#pragma unroll 8
        for (int k = 0; k < 32; k++) {
            float a0 = hs[buf][2*ty][k], a1 = hs[buf][2*ty+1][k];
            float4 b0 = *(const float4*)&Ws[buf][k][8*tx];
            float4 b1 = *(const float4*)&Ws[buf][k][8*tx + 4];
            float bv[8] = {b0.x,b0.y,b0.z,b0.w,b1.x,b1.y,b1.z,b1.w};
#pragma unroll
            for (int v = 0; v < 8; v++) {
                acc[0][v] = fmaf(a0, bv[v], acc[0][v]);
                acc[1][v] = fmaf(a1, bv[v], acc[1][v]);
            }
        }
    }

    float f1a[2] = {0.f, 0.f}, f2a[2] = {0.f, 0.f};
#pragma unroll
    for (int u = 0; u < 2; u++) {
        int row = i0 + 2*ty + u;
#pragma unroll
        for (int q = 0; q < 4; q++) {
            *(__half2*)&g_Wh16[(size_t)row * FOUT + 8*tx + 2*q] =
                __floats2half2_rn(acc[u][2*q], acc[u][2*q+1]);
        }
#pragma unroll
        for (int v = 0; v < 8; v++) {
            int col = 8*tx + v;
            f1a[u] = fmaf(acc[u][v], a[col],        f1a[u]);
            f2a[u] = fmaf(acc[u][v], a[FOUT + col], f2a[u]);
        }
    }
#pragma unroll
    for (int o = 8; o > 0; o >>= 1) {
        f1a[0] += __shfl_xor_sync(0xffffffffu, f1a[0], o);
        f1a[1] += __shfl_xor_sync(0xffffffffu, f1a[1], o);
        f2a[0] += __shfl_xor_sync(0xffffffffu, f2a[0], o);
        f2a[1] += __shfl_xor_sync(0xffffffffu, f2a[1], o);
    }
    if (tx == 0) {
        int k = (i0 >> 1) + ty;         // j-pair index for rows 2ty, 2ty+1
        uint2 a1v;
        a1v.x = h2u(__floats2half2_rn(f2a[0], f2a[1]));
        a1v.y = h2u(__floats2half2_rn(expf(f2a[0]), expf(f2a[1])));
        g_A1[k] = a1v;
        g_A2[k] = h2u(__floats2half2_rn(expf(0.2f*f2a[0]), expf(0.2f*f2a[1])));
#pragma unroll
        for (int u = 0; u < 2; u++) {
            int i = i0 + 2*ty + u;
            g_nf1h[i] = __float2half(-f1a[u]);
            g_H1h[i]  = __float2half(expf(-0.8f * f1a[u]));
        }
    }
}

// =====================================================================
// Kernel 2: fused masked-softmax-attention, fp16 mma.sync (R13 main,
// unchanged): R10 skeleton + packed-half2 pgen + fp32 shfl denominator.
// 512 threads (16 warps, 2m x 8n, m16n16), BM=32, grid 256.
// adj ring x3, sP x3, sB x4; commit [B(ch+2)][A(ch+3)] + wait_group 4;
// ONE __syncthreads per chunk.
// =====================================================================
__device__ __forceinline__ void mma_fp16(float* c, const uint32_t* a,
                                         uint32_t b0, uint32_t b1)
{
    asm volatile(
        "mma.sync.aligned.m16n8k16.row.col.f32.f16.f16.f32 "
        "{%0,%1,%2,%3},{%4,%5,%6,%7},{%8,%9},{%0,%1,%2,%3};\n"
        : "+f"(c[0]), "+f"(c[1]), "+f"(c[2]), "+f"(c[3])
        : "r"(a[0]), "r"(a[1]), "r"(a[2]), "r"(a[3]), "r"(b0), "r"(b1));
}

#define ADJ_SLOT 8192u       // 32 x 64 ints
#define SP_SLOT  4608u       // 32 x 72 halfs (144B rows)
#define SB_SLOT  17408u      // 64 x 136 halfs (272B rows)
#define DYN_SMEM (3*ADJ_SLOT + 3*SP_SLOT + 4*SB_SLOT)   // 108032

__global__ __launch_bounds__(512, 2) void gat_main_kernel(
    const int* __restrict__ adj, float* __restrict__ out)
{
    extern __shared__ char dynsm[];
    __shared__ float sden[BM];

    const int tid  = threadIdx.x;
    const int lane = tid & 31;
    const int warp = tid >> 5;     // 0..15
    const int r    = tid >> 4;     // 0..31  (pgen/adj row)
    const int cq   = tid & 15;     // col group of 4
    const int i0   = blockIdx.x * BM;
    const int wm   = warp & 1;     // m16 position (2)
    const int wn   = warp >> 1;    // n16 position (8)

    const uint32_t adjS = sptr(dynsm);
    const uint32_t spS  = adjS + 3 * ADJ_SLOT;
    const uint32_t sbS  = spS  + 3 * SP_SLOT;

    const __half2 nf1r2 = __half2half2(g_nf1h[i0 + r]);
    const __half2 H1r2  = __half2half2(g_H1h [i0 + r]);
    float den = 0.0f;

    float acc[2][4];
#pragma unroll
    for (int nf = 0; nf < 2; nf++)
#pragma unroll
        for (int q = 0; q < 4; q++) acc[nf][q] = 0.0f;

    // ---- stage helpers (each always commits exactly one group) ----
    auto stage_adj = [&](int ch) {
        if (ch < NC) {
            const int* src = &adj[(size_t)(i0 + r) * NN + ch * 64 + 4 * cq];
            uint32_t dst = adjS + (uint32_t)(ch % 3) * ADJ_SLOT
                         + (uint32_t)(r * 256 + 16 * cq);
            asm volatile("cp.async.cg.shared.global [%0],[%1],16;\n" :: "r"(dst), "l"(src));
        }
        asm volatile("cp.async.commit_group;\n");
    };
    auto stage_B = [&](int ch) {
        if (ch < NC) {
            const int j0 = ch * 64;
            uint32_t base = sbS + (uint32_t)(ch & 3) * SB_SLOT;
#pragma unroll
            for (int i = 0; i < 2; i++) {
                int seg = tid + 512 * i;          // 0..1023
                int rr = seg >> 4, ss = seg & 15;
                const __half* src = &g_Wh16[(size_t)(j0 + rr) * FOUT + 8 * ss];
                uint32_t dst = base + (uint32_t)(rr * 272 + 16 * ss);
                asm volatile("cp.async.cg.shared.global [%0],[%1],16;\n" :: "r"(dst), "l"(src));
            }
        }
        asm volatile("cp.async.commit_group;\n");
    };

    // pgen: packed half2 tables, mask-select; fp32 den from the SAME
    // fp16 weights the MMA consumes.
    auto pgen_rest = [&](int ch, uint4 t1, uint2 t2) {
        uint32_t aoff = adjS + (uint32_t)(ch % 3) * ADJ_SLOT
                      + (uint32_t)(r * 256 + 16 * cq);
        int4 a0;
        asm volatile("ld.shared.v4.b32 {%0,%1,%2,%3},[%4];"
                     : "=r"(a0.x), "=r"(a0.y), "=r"(a0.z), "=r"(a0.w) : "r"(aoff));
        uint32_t gA = __hgt2_mask(u2h(t1.x), nf1r2);
        uint32_t gB = __hgt2_mask(u2h(t1.z), nf1r2);
        uint32_t tA = h2u(__hmul2(H1r2, u2h(t2.x)));
        uint32_t tB = h2u(__hmul2(H1r2, u2h(t2.y)));
        uint32_t selA = (t1.y & gA) | (tA & ~gA);
        uint32_t selB = (t1.w & gB) | (tB & ~gB);
        uint32_t mA = (a0.x > 0 ? 0xFFFFu : 0u) | (a0.y > 0 ? 0xFFFF0000u : 0u);
        uint32_t mB = (a0.z > 0 ? 0xFFFFu : 0u) | (a0.w > 0 ? 0xFFFF0000u : 0u);
        uint32_t wA = selA & mA, wB = selB & mB;
        float2 fa = __half22float2(u2h(wA));
        float2 fb = __half22float2(u2h(wB));
        den += fa.x + fa.y + fb.x + fb.y;
        uint32_t dst = spS + (uint32_t)(ch % 3) * SP_SLOT
                     + (uint32_t)(r * 144 + 8 * cq);
        asm volatile("st.shared.v2.b32 [%0],{%1,%2};"
                     :: "r"(dst), "r"(wA), "r"(wB) : "memory");
    };

    auto mma_phase = [&](int ch) {
        uint32_t sp = spS + (uint32_t)(ch % 3) * SP_SLOT;
        uint32_t sb = sbS + (uint32_t)(ch & 3) * SB_SLOT;
        const int mi = lane >> 3, l7 = lane & 7;
        uint32_t spA = sp + (uint32_t)((16*wm + ((mi & 1) << 3) + l7) * 144
                                       + (((mi >> 1) << 3)) * 2);
        uint32_t sbB = sb + (uint32_t)((((mi & 1) << 3) + l7) * 272
                                       + (16*wn + ((mi >> 1) << 3)) * 2);
#pragma unroll
        for (int kk = 0; kk < 4; kk++) {
            uint32_t afr[4];
            asm volatile(
                "ldmatrix.sync.aligned.m8n8.x4.shared.b16 {%0,%1,%2,%3},[%4];\n"
                : "=r"(afr[0]), "=r"(afr[1]), "=r"(afr[2]), "=r"(afr[3])
                : "r"(spA + (uint32_t)(32 * kk)));
            uint32_t b[4];
            asm volatile(
                "ldmatrix.sync.aligned.m8n8.x4.trans.shared.b16 {%0,%1,%2,%3},[%4];\n"
                : "=r"(b[0]), "=r"(b[1]), "=r"(b[2]), "=r"(b[3])
                : "r"(sbB + (uint32_t)(16 * kk * 272)));
            mma_fp16(acc[0], afr, b[0], b[1]);
            mma_fp16(acc[1], afr, b[2], b[3]);
        }
    };

    // ---- prologue: commits [A0][B0][A1][B1][A2] ----
    stage_adj(0);
    stage_B(0);
    stage_adj(1);
    stage_B(1);
    stage_adj(2);
    {
        uint4 t1 = __ldg((const uint4*)&g_A1[2 * cq]);
        uint2 t2 = __ldg((const uint2*)&g_A2[2 * cq]);
        asm volatile("cp.async.wait_group 4;\n");   // forces A0
        pgen_rest(0, t1, t2);
    }

    // ---- main loop: commits per iter [B(ch+2)][A(ch+3)], 1 barrier ----
    for (int ch = 0; ch < NC; ch++) {
        stage_B(ch + 2);
        stage_adj(ch + 3);
        const int chn = ch + 1;
        uint4 t1; uint2 t2;
        if (chn < NC) {                 // hoisted: no cp.async dependency
            t1 = __ldg((const uint4*)&g_A1[chn * 32 + 2 * cq]);
            t2 = __ldg((const uint2*)&g_A2[chn * 32 + 2 * cq]);
        }
        asm volatile("cp.async.wait_group 4;\n");   // forces B(ch), A(ch+1)
        if (chn < NC) pgen_rest(chn, t1, t2);
        __syncthreads();                // publishes P(ch)/B(ch); guards reuse
        mma_phase(ch);
    }

    // ---- denominator reduction (16 threads per row) ----
    den += __shfl_xor_sync(0xffffffffu, den, 1);
    den += __shfl_xor_sync(0xffffffffu, den, 2);
    den += __shfl_xor_sync(0xffffffffu, den, 4);
    den += __shfl_xor_sync(0xffffffffu, den, 8);
    if (cq == 0) sden[r] = den;
    __syncthreads();

    // ---- epilogue: normalize, write fp32 output ----
    const int g = lane >> 2, t = lane & 3;
    {
        int row0 = 16*wm + g;
        float inv0 = 1.0f / sden[row0];
        float inv1 = 1.0f / sden[row0 + 8];
#pragma unroll
        for (int nf = 0; nf < 2; nf++) {
            int col = 16*wn + 8*nf + 2*t;
            out[(size_t)(i0 + row0)     * FOUT + col    ] = acc[nf][0] * inv0;
            out[(size_t)(i0 + row0)     * FOUT + col + 1] = acc[nf][1] * inv0;
            out[(size_t)(i0 + row0 + 8) * FOUT + col    ] = acc[nf][2] * inv1;
            out[(size_t)(i0 + row0 + 8) * FOUT + col + 1] = acc[nf][3] * inv1;
        }
    }
}

// =====================================================================
extern "C" void kernel_launch(void* const* d_in, const int* in_sizes, int n_in,
                              void* d_out, int out_size)
{
    const float* h   = (const float*)d_in[0];   // [8192,256] f32
    const int*   adj = (const int*)  d_in[1];   // [8192,8192] i32
    const float* Wm  = (const float*)d_in[2];   // [256,128] f32
    const float* a   = (const float*)d_in[3];   // [256,1] f32
    float* out = (float*)d_out;                 // [8192,128] f32

    cudaFuncSetAttribute(gat_main_kernel,
                         cudaFuncAttributeMaxDynamicSharedMemorySize, DYN_SMEM);

    wh_gemm_kernel <<<256, 256>>>(h, Wm, a);
    gat_main_kernel<<<GRID_MAIN, 512, DYN_SMEM>>>(adj, out);
}